// round 3
// baseline (speedup 1.0000x reference)
#include <cuda_runtime.h>
#include <math.h>

// Problem shape (fixed by setup_inputs)
#define B_ 4
#define S_ 4096
#define H_ 768
#define E_ 64

// Scratch (device globals: allocation-free per harness rules)
__device__ float g_q[(size_t)B_ * S_ * H_];
__device__ float g_k[(size_t)B_ * S_ * H_];
__device__ float g_v[(size_t)B_ * S_ * H_];
__device__ float g_scores[(size_t)B_ * S_ * S_];   // 256 MB
__device__ float g_colbias[B_ * S_];

// ---------------------------------------------------------------------------
// Column-bias prep: colbias[b][s] = (1-mask)*-10000 + (#entity hits at s)
// ---------------------------------------------------------------------------
__global__ void bias_init_kernel(const float* __restrict__ mask)
{
    int i = blockIdx.x * blockDim.x + threadIdx.x;
    if (i < B_ * S_) g_colbias[i] = (1.0f - mask[i]) * -10000.0f;
}

__global__ void bias_scatter_kernel(const int* __restrict__ epos)
{
    int i = threadIdx.x;
    if (i < B_ * E_) {
        int b = i / E_;
        // exact small-integer adds -> order-independent, deterministic
        atomicAdd(&g_colbias[b * S_ + epos[i]], 1.0f);
    }
}

// ---------------------------------------------------------------------------
// Tiled SGEMM body: C = A * op(B), 128x128 block, 8x8/thread, BK=8,
// double-buffered smem.
//   BT=true : B is N x K row-major (NT gemm, dot of rows)  -- QKV, scores
//   BT=false: B is K x N row-major (NN gemm)               -- P @ V
//   EPI=0: C = acc + aux[col]          (QKV bias)
//   EPI=1: C = acc*alpha + aux[col]    (scores scale + column bias)
//   EPI=2: C = acc                     (PV)
// All dims are exact multiples of the tile => no bounds checks.
// ---------------------------------------------------------------------------
constexpr int BM = 128, BN = 128, BK = 8, TM = 8, TN = 8, PAD = 4;

template <bool BT, int EPI>
__device__ __forceinline__
void sgemm_body(const float* __restrict__ A, const float* __restrict__ Bm,
                float* __restrict__ C,
                int K, int lda, int ldb, int ldc,
                const float* __restrict__ auxp, float alpha)
{
    __shared__ float As[2][BK][BM + PAD];
    __shared__ float Bs[2][BK][BN + PAD];

    const int tid = threadIdx.x;
    const int tx = tid & 15;
    const int ty = tid >> 4;
    const int rowBase = blockIdx.y * BM;
    const int colBase = blockIdx.x * BN;

    // load mapping: 256 threads, 128x8 tile => one float4 per thread
    const int arow = tid >> 1;
    const int acol = (tid & 1) * 4;
    int brow, bcol;
    if (BT) { brow = tid >> 1; bcol = (tid & 1) * 4; }    // brow = n index, bcol = k
    else    { brow = tid >> 5; bcol = (tid & 31) * 4; }   // brow = k index, bcol = n

    const float* Aptr = A + (long long)(rowBase + arow) * lda + acol;
    const float* Bptr = BT ? (Bm + (long long)(colBase + brow) * ldb + bcol)
                           : (Bm + (long long)brow * ldb + colBase + bcol);

    float acc[TM][TN] = {};

    // first tile -> buffer 0
    float4 av = *reinterpret_cast<const float4*>(Aptr);
    float4 bv = *reinterpret_cast<const float4*>(Bptr);
    As[0][acol + 0][arow] = av.x;
    As[0][acol + 1][arow] = av.y;
    As[0][acol + 2][arow] = av.z;
    As[0][acol + 3][arow] = av.w;
    if (BT) {
        Bs[0][bcol + 0][brow] = bv.x;
        Bs[0][bcol + 1][brow] = bv.y;
        Bs[0][bcol + 2][brow] = bv.z;
        Bs[0][bcol + 3][brow] = bv.w;
    } else {
        *reinterpret_cast<float4*>(&Bs[0][brow][bcol]) = bv;
    }
    __syncthreads();

    int buf = 0;
    for (int kt = 0; kt < K; kt += BK) {
        const bool more = (kt + BK) < K;
        if (more) {
            av = *reinterpret_cast<const float4*>(Aptr + kt + BK);
            if (BT) bv = *reinterpret_cast<const float4*>(Bptr + kt + BK);
            else    bv = *reinterpret_cast<const float4*>(Bptr + (long long)(kt + BK) * ldb);
        }
#pragma unroll
        for (int kk = 0; kk < BK; kk++) {
            float4 a0 = *reinterpret_cast<const float4*>(&As[buf][kk][ty * TM]);
            float4 a1 = *reinterpret_cast<const float4*>(&As[buf][kk][ty * TM + 4]);
            float4 b0 = *reinterpret_cast<const float4*>(&Bs[buf][kk][tx * TN]);
            float4 b1 = *reinterpret_cast<const float4*>(&Bs[buf][kk][tx * TN + 4]);
            float af[TM] = {a0.x, a0.y, a0.z, a0.w, a1.x, a1.y, a1.z, a1.w};
            float bf[TN] = {b0.x, b0.y, b0.z, b0.w, b1.x, b1.y, b1.z, b1.w};
#pragma unroll
            for (int i = 0; i < TM; i++)
#pragma unroll
                for (int j = 0; j < TN; j++)
                    acc[i][j] = fmaf(af[i], bf[j], acc[i][j]);
        }
        if (more) {
            const int nb = buf ^ 1;
            As[nb][acol + 0][arow] = av.x;
            As[nb][acol + 1][arow] = av.y;
            As[nb][acol + 2][arow] = av.z;
            As[nb][acol + 3][arow] = av.w;
            if (BT) {
                Bs[nb][bcol + 0][brow] = bv.x;
                Bs[nb][bcol + 1][brow] = bv.y;
                Bs[nb][bcol + 2][brow] = bv.z;
                Bs[nb][bcol + 3][brow] = bv.w;
            } else {
                *reinterpret_cast<float4*>(&Bs[nb][brow][bcol]) = bv;
            }
        }
        __syncthreads();
        buf ^= 1;
    }

    float auxv[TN];
    if (EPI < 2) {
#pragma unroll
        for (int j = 0; j < TN; j++) auxv[j] = auxp[colBase + tx * TN + j];
    }
#pragma unroll
    for (int i = 0; i < TM; i++) {
        float* cp = C + (long long)(rowBase + ty * TM + i) * ldc + colBase + tx * TN;
        float o[TN];
#pragma unroll
        for (int j = 0; j < TN; j++) {
            float vv = acc[i][j];
            if (EPI == 0)      vv = vv + auxv[j];
            else if (EPI == 1) vv = vv * alpha + auxv[j];
            o[j] = vv;
        }
        *reinterpret_cast<float4*>(cp)     = make_float4(o[0], o[1], o[2], o[3]);
        *reinterpret_cast<float4*>(cp + 4) = make_float4(o[4], o[5], o[6], o[7]);
    }
}

// ---- thin wrappers: device globals referenced directly (no symbol lookup) --
template <int SEL>
__global__ __launch_bounds__(256)
void qkv_kernel(const float* __restrict__ hs, const float* __restrict__ W,
                const float* __restrict__ bias)
{
    float* out = (SEL == 0) ? g_q : (SEL == 1) ? g_k : g_v;
    sgemm_body<true, 0>(hs, W, out, H_, H_, H_, H_, bias, 1.0f);
}

__global__ __launch_bounds__(256)
void scores_kernel(float alpha)
{
    const int bz = blockIdx.z;
    sgemm_body<true, 1>(g_q + (long long)bz * S_ * H_,
                        g_k + (long long)bz * S_ * H_,
                        g_scores + (long long)bz * S_ * S_,
                        H_, H_, H_, S_,
                        g_colbias + bz * S_, alpha);
}

__global__ __launch_bounds__(256)
void pv_kernel(float* __restrict__ out)
{
    const int bz = blockIdx.z;
    sgemm_body<false, 2>(g_scores + (long long)bz * S_ * S_,
                         g_v + (long long)bz * S_ * H_,
                         out + (long long)bz * S_ * H_,
                         S_, S_, H_, H_, nullptr, 1.0f);
}

// ---------------------------------------------------------------------------
// Row softmax over S_=4096 columns. One block per row, values held in regs:
// exactly one read + one write of the 256 MB scores buffer.
// ---------------------------------------------------------------------------
__global__ void softmax_rows()
{
    const long long row = blockIdx.x;
    float4* p4 = reinterpret_cast<float4*>(g_scores + row * (long long)S_);
    const int t = threadIdx.x;
    const int lane = t & 31, w = t >> 5;

    float4 v[4];
    float m = -1e30f;
#pragma unroll
    for (int i = 0; i < 4; i++) {
        v[i] = p4[t + i * 256];
        m = fmaxf(m, fmaxf(fmaxf(v[i].x, v[i].y), fmaxf(v[i].z, v[i].w)));
    }

    __shared__ float sh[8];
    __shared__ float bres;
#pragma unroll
    for (int o = 16; o; o >>= 1) m = fmaxf(m, __shfl_xor_sync(0xffffffffu, m, o));
    if (!lane) sh[w] = m;
    __syncthreads();
    if (t == 0) {
        float mm = sh[0];
#pragma unroll
        for (int i = 1; i < 8; i++) mm = fmaxf(mm, sh[i]);
        bres = mm;
    }
    __syncthreads();
    m = bres;

    float s = 0.f;
#pragma unroll
    for (int i = 0; i < 4; i++) {
        v[i].x = __expf(v[i].x - m);
        v[i].y = __expf(v[i].y - m);
        v[i].z = __expf(v[i].z - m);
        v[i].w = __expf(v[i].w - m);
        s += (v[i].x + v[i].y) + (v[i].z + v[i].w);
    }
#pragma unroll
    for (int o = 16; o; o >>= 1) s += __shfl_xor_sync(0xffffffffu, s, o);
    if (!lane) sh[w] = s;
    __syncthreads();
    if (t == 0) {
        float ss = 0.f;
#pragma unroll
        for (int i = 0; i < 8; i++) ss += sh[i];
        bres = ss;
    }
    __syncthreads();
    const float inv = 1.0f / bres;
#pragma unroll
    for (int i = 0; i < 4; i++) {
        v[i].x *= inv; v[i].y *= inv; v[i].z *= inv; v[i].w *= inv;
        p4[t + i * 256] = v[i];
    }
}

// ---------------------------------------------------------------------------
extern "C" void kernel_launch(void* const* d_in, const int* in_sizes, int n_in,
                              void* d_out, int out_size)
{
    const float* hs   = (const float*)d_in[0];
    const float* mask = (const float*)d_in[1];
    const int*   epos = (const int*)d_in[2];
    const float* Wq   = (const float*)d_in[3];
    const float* bq   = (const float*)d_in[4];
    const float* Wk   = (const float*)d_in[5];
    const float* bk   = (const float*)d_in[6];
    const float* Wv   = (const float*)d_in[7];
    const float* bv   = (const float*)d_in[8];
    float* out = (float*)d_out;

    // 1) column bias (mask fold + entity scatter)
    bias_init_kernel<<<(B_ * S_ + 255) / 256, 256>>>(mask);
    bias_scatter_kernel<<<1, 256>>>(epos);

    const int M = B_ * S_;
    dim3 blk(256);

    // 2) QKV projections: NT gemm, bias epilogue
    qkv_kernel<0><<<dim3(H_ / BN, M / BM, 1), blk>>>(hs, Wq, bq);
    qkv_kernel<1><<<dim3(H_ / BN, M / BM, 1), blk>>>(hs, Wk, bk);
    qkv_kernel<2><<<dim3(H_ / BN, M / BM, 1), blk>>>(hs, Wv, bv);

    // 3) scores = (Q Kt)/sqrt(H) + colbias   (batched NT gemm)
    const float alpha = 1.0f / sqrtf((float)H_);
    scores_kernel<<<dim3(S_ / BN, S_ / BM, B_), blk>>>(alpha);

    // 4) row softmax
    softmax_rows<<<B_ * S_, 256>>>();

    // 5) context = P V   (batched NN gemm) -> d_out
    pv_kernel<<<dim3(H_ / BN, S_ / BM, B_), blk>>>(out);
}